// round 3
// baseline (speedup 1.0000x reference)
#include <cuda_runtime.h>
#include <math.h>

// Problem constants
#define BATCH   8
#define HDIM    32
#define WDIM    32
#define NC      384
#define NGROUP  6
#define NHEAD   12
#define HC      32
#define GC      64
#define NPOS    1024            // H*W
#define MTOT    (BATCH * NPOS)  // 8192

// ---------------- device scratch (static allocations are allowed) ----------
__device__ float g_q  [MTOT * NC];
__device__ float g_t  [MTOT * NC];
__device__ float g_warp[BATCH * NGROUP * NPOS * 2];
__device__ float g_xs [MTOT * NC];
__device__ float g_k  [MTOT * NC];
__device__ float g_v  [MTOT * NC];
__device__ float g_ao [MTOT * NC];

// ======================================================================
// Generic GEMM: C[M,N] = A[M,K] @ W[K,N] + bias[N]
// BM=128, BN=64, BK=16, 256 threads, 8x4 per-thread microtile.
// Requires M%128==0, N%64==0, K%16==0 (true for all uses here).
// ======================================================================
__global__ void __launch_bounds__(256) gemm_bias_kernel(
    const float* __restrict__ A, const float* __restrict__ W,
    const float* __restrict__ bias, float* __restrict__ C,
    int M, int N, int K)
{
    __shared__ float As[16][132];   // [k][m] (transposed), float4-aligned rows
    __shared__ float Bs[16][68];    // [k][n]

    const int tid = threadIdx.x;
    const int tx  = tid & 15;       // col group: cols tx*4 .. tx*4+3
    const int ty  = tid >> 4;       // row group: rows ty*8 .. ty*8+7
    const int bm  = blockIdx.y * 128;
    const int bn  = blockIdx.x * 64;

    float acc[8][4];
#pragma unroll
    for (int i = 0; i < 8; i++)
#pragma unroll
        for (int j = 0; j < 4; j++) acc[i][j] = 0.f;

    for (int kt = 0; kt < K; kt += 16) {
#pragma unroll
        for (int l = 0; l < 8; l++) {
            int e  = tid + l * 256;
            int ar = e >> 4, ac = e & 15;
            As[ac][ar] = A[(size_t)(bm + ar) * K + kt + ac];
        }
#pragma unroll
        for (int l = 0; l < 4; l++) {
            int e  = tid + l * 256;
            int kr = e >> 6, nc = e & 63;
            Bs[kr][nc] = W[(size_t)(kt + kr) * N + bn + nc];
        }
        __syncthreads();
#pragma unroll
        for (int k = 0; k < 16; k++) {
            float4 a0 = *(const float4*)&As[k][ty * 8];
            float4 a1 = *(const float4*)&As[k][ty * 8 + 4];
            float4 bv = *(const float4*)&Bs[k][tx * 4];
            float a[8] = {a0.x, a0.y, a0.z, a0.w, a1.x, a1.y, a1.z, a1.w};
            float bb[4] = {bv.x, bv.y, bv.z, bv.w};
#pragma unroll
            for (int i = 0; i < 8; i++)
#pragma unroll
                for (int j = 0; j < 4; j++) acc[i][j] += a[i] * bb[j];
        }
        __syncthreads();
    }

    float4 bias4 = *(const float4*)&bias[bn + tx * 4];
#pragma unroll
    for (int i = 0; i < 8; i++) {
        int row = bm + ty * 8 + i;
        float4 o;
        o.x = acc[i][0] + bias4.x;
        o.y = acc[i][1] + bias4.y;
        o.z = acc[i][2] + bias4.z;
        o.w = acc[i][3] + bias4.w;
        *(float4*)&C[(size_t)row * N + bn + tx * 4] = o;
    }
}

// ======================================================================
// Grouped 3x3 conv (SAME, zero pad) on g_q as implicit GEMM:
// per group g: t[:, g*64 .. g*64+63] = im2col(q_g)[8192, 576] @ Wg[576,64] + b
// grid: (M/128, 6 groups); same tiling as gemm_bias_kernel.
// w_off0 layout [3,3,64,384]: flat ((kh*3+kw)*64 + ic)*384 + oc, so patch
// index kk = tap*64 + ic maps directly to row kk of the weight matrix.
// ======================================================================
__global__ void __launch_bounds__(256) conv_off_kernel(
    const float* __restrict__ Wc, const float* __restrict__ bias)
{
    __shared__ float As[16][132];
    __shared__ float Bs[16][68];

    const int tid = threadIdx.x;
    const int tx  = tid & 15;
    const int ty  = tid >> 4;
    const int bm  = blockIdx.x * 128;   // position tile (never crosses batch)
    const int g   = blockIdx.y;
    const int b   = bm >> 10;

    float acc[8][4];
#pragma unroll
    for (int i = 0; i < 8; i++)
#pragma unroll
        for (int j = 0; j < 4; j++) acc[i][j] = 0.f;

    for (int kt = 0; kt < 576; kt += 16) {
        const int tap = kt >> 6;          // constant over the 16-wide slice
        const int dy  = tap / 3 - 1;
        const int dx  = tap % 3 - 1;
#pragma unroll
        for (int l = 0; l < 8; l++) {
            int e  = tid + l * 256;
            int ar = e >> 4, ac = e & 15;
            int ij = (bm + ar) & 1023;
            int i0 = ij >> 5, j0 = ij & 31;
            int ii = i0 + dy, jj = j0 + dx;
            int ic = (kt + ac) & 63;
            float v = 0.f;
            if ((unsigned)ii < 32u && (unsigned)jj < 32u)
                v = g_q[(size_t)((b << 10) + (ii << 5) + jj) * NC + g * 64 + ic];
            As[ac][ar] = v;
        }
#pragma unroll
        for (int l = 0; l < 4; l++) {
            int e  = tid + l * 256;
            int kr = e >> 6, nc = e & 63;
            Bs[kr][nc] = Wc[(size_t)(kt + kr) * NC + g * 64 + nc];
        }
        __syncthreads();
#pragma unroll
        for (int k = 0; k < 16; k++) {
            float4 a0 = *(const float4*)&As[k][ty * 8];
            float4 a1 = *(const float4*)&As[k][ty * 8 + 4];
            float4 bv = *(const float4*)&Bs[k][tx * 4];
            float a[8] = {a0.x, a0.y, a0.z, a0.w, a1.x, a1.y, a1.z, a1.w};
            float bb[4] = {bv.x, bv.y, bv.z, bv.w};
#pragma unroll
            for (int i = 0; i < 8; i++)
#pragma unroll
                for (int j = 0; j < 4; j++) acc[i][j] += a[i] * bb[j];
        }
        __syncthreads();
    }

    float4 bias4 = *(const float4*)&bias[g * 64 + tx * 4];
#pragma unroll
    for (int i = 0; i < 8; i++) {
        int row = bm + ty * 8 + i;
        float4 o;
        o.x = acc[i][0] + bias4.x;
        o.y = acc[i][1] + bias4.y;
        o.z = acc[i][2] + bias4.z;
        o.w = acc[i][3] + bias4.w;
        *(float4*)&g_t[(size_t)row * NC + g * 64 + tx * 4] = o;
    }
}

// ======================================================================
// LayerNorm (eps=1e-3) -> erf GELU -> per-group 64->2 projection ->
// tanh * 16 + reference point -> warp (x,y) coords.
// One block per spatial position, 128 threads.
// Reference-point quirk: ref[i,j] = (j, i); warp_x = pos[...,1] = tanh(o1)*16+i,
//                                            warp_y = pos[...,0] = tanh(o0)*16+j.
// ======================================================================
__global__ void __launch_bounds__(128) ln_offset_kernel(
    const float* __restrict__ ln_g, const float* __restrict__ ln_b,
    const float* __restrict__ w_offp)
{
    const int p  = blockIdx.x;            // 0..8191
    const int b  = p >> 10;
    const int ij = p & 1023;
    const int i0 = ij >> 5;
    const int j0 = ij & 31;
    const int tid = threadIdx.x;

    __shared__ float ts[NC];
    __shared__ float red[4];

    float lsum = 0.f;
    for (int c = tid; c < NC; c += 128) {
        float v = g_t[(size_t)p * NC + c];
        ts[c] = v;
        lsum += v;
    }
#pragma unroll
    for (int o = 16; o; o >>= 1) lsum += __shfl_xor_sync(0xffffffffu, lsum, o);
    if ((tid & 31) == 0) red[tid >> 5] = lsum;
    __syncthreads();
    const float mu = (red[0] + red[1] + red[2] + red[3]) * (1.f / NC);

    float lsq = 0.f;
    for (int c = tid; c < NC; c += 128) {
        float d = ts[c] - mu;
        lsq += d * d;
    }
#pragma unroll
    for (int o = 16; o; o >>= 1) lsq += __shfl_xor_sync(0xffffffffu, lsq, o);
    __syncthreads();                 // all mu reads done before red reuse
    if ((tid & 31) == 0) red[tid >> 5] = lsq;
    __syncthreads();
    const float var  = (red[0] + red[1] + red[2] + red[3]) * (1.f / NC);
    const float rstd = rsqrtf(var + 1e-3f);

    for (int c = tid; c < NC; c += 128) {
        float y = (ts[c] - mu) * rstd * ln_g[c] + ln_b[c];
        ts[c] = 0.5f * y * (1.f + erff(y * 0.7071067811865476f));  // erf GELU
    }
    __syncthreads();

    if (tid < 12) {
        int g    = tid >> 1;
        int comp = tid & 1;
        float o = 0.f;
        for (int cc = 0; cc < 64; cc++)
            o += ts[g * 64 + cc] * w_offp[cc * 2 + comp];
        float t = tanhf(o) * 16.0f;                 // offset_range = H/2 = W/2 = 16
        float val = (comp == 0) ? (t + (float)j0)   // pos0 -> warp_y (slot 1)
                                : (t + (float)i0);  // pos1 -> warp_x (slot 0)
        g_warp[(size_t)(((b * NGROUP + g) << 10) + ij) * 2 + (1 - comp)] = val;
    }
}

// ======================================================================
// Bilinear sample with zero border (pad-by-1 semantics, clip-floor,
// clip-frac), exactly matching the reference formula.
// grid (256 qtiles, 48 bg), 256 threads = 4 queries x 64 channels.
// ======================================================================
__device__ __forceinline__ float fetch_x(const float* __restrict__ x,
                                         int b, int ch, int yy, int xx)
{
    int ri = yy - 1, rj = xx - 1;      // padded -> original coords
    if ((unsigned)ri >= 32u || (unsigned)rj >= 32u) return 0.f;
    return x[(size_t)((b << 10) + (ri << 5) + rj) * NC + ch];
}

__global__ void __launch_bounds__(256) sample_kernel(const float* __restrict__ x)
{
    const int bg   = blockIdx.y;                       // 0..47
    const int b    = bg / NGROUP;
    const int g    = bg % NGROUP;
    const int qidx = blockIdx.x * 4 + (threadIdx.x >> 6);
    const int cc   = threadIdx.x & 63;
    const int ch   = g * 64 + cc;

    const float wx = g_warp[(size_t)((bg << 10) + qidx) * 2 + 0];
    const float wy = g_warp[(size_t)((bg << 10) + qidx) * 2 + 1];

    const float xq = wx + 1.f;
    const float yq = wy + 1.f;
    float y0f = fminf(fmaxf(floorf(yq), 0.f), 32.f);
    float x0f = fminf(fmaxf(floorf(xq), 0.f), 32.f);
    float ay  = fminf(fmaxf(yq - y0f, 0.f), 1.f);
    float ax  = fminf(fmaxf(xq - x0f, 0.f), 1.f);
    int y0 = (int)y0f, x0 = (int)x0f;

    float tl = fetch_x(x, b, ch, y0,     x0);
    float tr = fetch_x(x, b, ch, y0,     x0 + 1);
    float bl = fetch_x(x, b, ch, y0 + 1, x0);
    float br = fetch_x(x, b, ch, y0 + 1, x0 + 1);

    float top = tl + ax * (tr - tl);
    float bot = bl + ax * (br - bl);
    float v   = top + ay * (bot - top);

    g_xs[(size_t)((b << 10) + qidx) * NC + ch] = v;
}

// ======================================================================
// Attention: one block per (b, h, 16-query tile). Scores for all 1024
// keys kept in smem (row stride 1025 to kill bank conflicts), exact
// softmax, then P@V with per-warp key partitions + smem reduction.
// dyn smem = 92480 B -> 2 blocks/SM.
// ======================================================================
__global__ void __launch_bounds__(256) attn_kernel()
{
    const int qt = blockIdx.x;      // 0..63
    const int h  = blockIdx.y;      // 0..11
    const int b  = blockIdx.z;      // 0..7

    extern __shared__ float sm[];
    float* ss   = sm;               // 16 x 1025
    float* qsm  = ss + 16 * 1025;   // 16 x 32
    float* kvs  = qsm + 512;        // 64 x 33
    float* rbuf = kvs + 64 * 33;    // 8 x 512

    const int tid   = threadIdx.x;
    const int qbase = qt * 16;

    for (int e = tid; e < 512; e += 256) {
        int r = e >> 5, c = e & 31;
        qsm[e] = g_q[(size_t)((b << 10) + qbase + r) * NC + h * HC + c];
    }
    __syncthreads();

    // ---- pass 1: S = Q K^T * scale ----
    const int ty  = tid >> 5;       // q rows 2ty, 2ty+1
    const int txk = tid & 31;       // keys 2txk, 2txk+1 within 64-chunk
    float qa[32], qb[32];
#pragma unroll
    for (int c = 0; c < 32; c++) {
        qa[c] = qsm[(2 * ty) * 32 + c];
        qb[c] = qsm[(2 * ty + 1) * 32 + c];
    }
    const float scale = 0.17677669529663687f;  // 32^-0.5

    for (int kc = 0; kc < 1024; kc += 64) {
        for (int e = tid; e < 2048; e += 256) {
            int kr = e >> 5, c = e & 31;
            kvs[kr * 33 + c] = g_k[(size_t)((b << 10) + kc + kr) * NC + h * HC + c];
        }
        __syncthreads();
        float a00 = 0.f, a01 = 0.f, a10 = 0.f, a11 = 0.f;
        const int k0 = 2 * txk, k1 = 2 * txk + 1;
#pragma unroll
        for (int c = 0; c < 32; c++) {
            float kk0 = kvs[k0 * 33 + c];
            float kk1 = kvs[k1 * 33 + c];
            a00 += qa[c] * kk0;  a01 += qa[c] * kk1;
            a10 += qb[c] * kk0;  a11 += qb[c] * kk1;
        }
        ss[(2 * ty)     * 1025 + kc + k0] = a00 * scale;
        ss[(2 * ty)     * 1025 + kc + k1] = a01 * scale;
        ss[(2 * ty + 1) * 1025 + kc + k0] = a10 * scale;
        ss[(2 * ty + 1) * 1025 + kc + k1] = a11 * scale;
        __syncthreads();
    }

    // ---- softmax: warp w handles rows 2w, 2w+1 ----
    {
        const int w = tid >> 5, lane = tid & 31;
#pragma unroll
        for (int rr = 0; rr < 2; rr++) {
            float* row = ss + (2 * w + rr) * 1025;
            float m = -1e30f;
            for (int i = lane; i < 1024; i += 32) m = fmaxf(m, row[i]);
#pragma unroll
            for (int o = 16; o; o >>= 1) m = fmaxf(m, __shfl_xor_sync(0xffffffffu, m, o));
            float s = 0.f;
            for (int i = lane; i < 1024; i += 32) {
                float e = expf(row[i] - m);
                row[i] = e;
                s += e;
            }
#pragma unroll
            for (int o = 16; o; o >>= 1) s += __shfl_xor_sync(0xffffffffu, s, o);
            float rs = 1.f / s;
            for (int i = lane; i < 1024; i += 32) row[i] *= rs;
        }
    }
    __syncthreads();

    // ---- pass 2: O = P V, warp w owns keys w*8..w*8+7 in each chunk ----
    const int w  = tid >> 5;
    const int t  = tid & 31;
    const int rp = t >> 3;          // rows 4rp..4rp+3
    const int cp = t & 7;           // cols 4cp..4cp+3
    float oacc[4][4];
#pragma unroll
    for (int i = 0; i < 4; i++)
#pragma unroll
        for (int j = 0; j < 4; j++) oacc[i][j] = 0.f;

    for (int kc = 0; kc < 1024; kc += 64) {
        for (int e = tid; e < 2048; e += 256) {
            int kr = e >> 5, c = e & 31;
            kvs[kr * 33 + c] = g_v[(size_t)((b << 10) + kc + kr) * NC + h * HC + c];
        }
        __syncthreads();
#pragma unroll
        for (int kk = 0; kk < 8; kk++) {
            int kl = w * 8 + kk;
            float p0 = ss[(4 * rp + 0) * 1025 + kc + kl];
            float p1 = ss[(4 * rp + 1) * 1025 + kc + kl];
            float p2 = ss[(4 * rp + 2) * 1025 + kc + kl];
            float p3 = ss[(4 * rp + 3) * 1025 + kc + kl];
            float v0 = kvs[kl * 33 + 4 * cp + 0];
            float v1 = kvs[kl * 33 + 4 * cp + 1];
            float v2 = kvs[kl * 33 + 4 * cp + 2];
            float v3 = kvs[kl * 33 + 4 * cp + 3];
            oacc[0][0] += p0 * v0; oacc[0][1] += p0 * v1; oacc[0][2] += p0 * v2; oacc[0][3] += p0 * v3;
            oacc[1][0] += p1 * v0; oacc[1][1] += p1 * v1; oacc[1][2] += p1 * v2; oacc[1][3] += p1 * v3;
            oacc[2][0] += p2 * v0; oacc[2][1] += p2 * v1; oacc[2][2] += p2 * v2; oacc[2][3] += p2 * v3;
            oacc[3][0] += p3 * v0; oacc[3][1] += p3 * v1; oacc[3][2] += p3 * v2; oacc[3][3] += p3 * v3;
        }
        __syncthreads();
    }

#pragma unroll
    for (int i = 0; i < 4; i++)
#pragma unroll
        for (int j = 0; j < 4; j++)
            rbuf[w * 512 + (4 * rp + i) * 32 + 4 * cp + j] = oacc[i][j];
    __syncthreads();

    for (int e = tid; e < 512; e += 256) {
        float s = 0.f;
#pragma unroll
        for (int ww = 0; ww < 8; ww++) s += rbuf[ww * 512 + e];
        int r = e >> 5, c = e & 31;
        g_ao[(size_t)((b << 10) + qbase + r) * NC + h * HC + c] = s;
    }
}

// ======================================================================
// Host launcher
// ======================================================================
extern "C" void kernel_launch(void* const* d_in, const int* in_sizes, int n_in,
                              void* d_out, int out_size)
{
    (void)in_sizes; (void)n_in; (void)out_size;
    const float* x      = (const float*)d_in[0];
    const float* w_q    = (const float*)d_in[1];
    const float* b_q    = (const float*)d_in[2];
    const float* w_off0 = (const float*)d_in[3];
    const float* b_off0 = (const float*)d_in[4];
    const float* ln_g   = (const float*)d_in[5];
    const float* ln_b   = (const float*)d_in[6];
    const float* w_offp = (const float*)d_in[7];
    const float* w_k    = (const float*)d_in[8];
    const float* b_k    = (const float*)d_in[9];
    const float* w_v    = (const float*)d_in[10];
    const float* b_v    = (const float*)d_in[11];
    const float* w_o    = (const float*)d_in[12];
    const float* b_o    = (const float*)d_in[13];
    float* out = (float*)d_out;

    float *pq, *pxs, *pk, *pv, *pao;
    cudaGetSymbolAddress((void**)&pq,  g_q);
    cudaGetSymbolAddress((void**)&pxs, g_xs);
    cudaGetSymbolAddress((void**)&pk,  g_k);
    cudaGetSymbolAddress((void**)&pv,  g_v);
    cudaGetSymbolAddress((void**)&pao, g_ao);

    const dim3 gemm_grid(NC / 64, MTOT / 128);   // (6, 64)

    // 1) q = x @ w_q + b_q
    gemm_bias_kernel<<<gemm_grid, 256>>>(x, w_q, b_q, pq, MTOT, NC, NC);
    // 2) offset-branch grouped conv -> g_t
    conv_off_kernel<<<dim3(MTOT / 128, NGROUP), 256>>>(w_off0, b_off0);
    // 3) LN + GELU + offset proj + warp coords
    ln_offset_kernel<<<MTOT, 128>>>(ln_g, ln_b, w_offp);
    // 4) bilinear sampling of x -> g_xs
    sample_kernel<<<dim3(256, BATCH * NGROUP), 256>>>(x);
    // 5) k, v projections
    gemm_bias_kernel<<<gemm_grid, 256>>>(pxs, w_k, b_k, pk, MTOT, NC, NC);
    gemm_bias_kernel<<<gemm_grid, 256>>>(pxs, w_v, b_v, pv, MTOT, NC, NC);
    // 6) attention
    const int attn_smem = (16 * 1025 + 512 + 64 * 33 + 8 * 512) * (int)sizeof(float);
    cudaFuncSetAttribute(attn_kernel, cudaFuncAttributeMaxDynamicSharedMemorySize, attn_smem);
    attn_kernel<<<dim3(64, NHEAD, BATCH), 256, attn_smem>>>();
    // 7) y = attn_out @ w_o + b_o
    gemm_bias_kernel<<<gemm_grid, 256>>>(pao, w_o, b_o, out, MTOT, NC, NC);
}

// round 6
// speedup vs baseline: 1.9018x; 1.9018x over previous
#include <cuda_runtime.h>
#include <math.h>
#include <stdint.h>

// Problem constants
#define BATCH   8
#define NC      384
#define NGROUP  6
#define NHEAD   12
#define HC      32
#define GC      64
#define NPOS    1024
#define MTOT    (BATCH * NPOS)  // 8192

// ---------------- device scratch ----------
__device__ float g_q  [MTOT * NC];
__device__ float g_t  [MTOT * NC];
__device__ float g_warp[BATCH * NGROUP * NPOS * 2];
__device__ float g_xs [MTOT * NC];
__device__ float g_k  [MTOT * NC];
__device__ float g_v  [MTOT * NC];
__device__ float g_ao [MTOT * NC];

// ---------------- tf32 mma helpers ----------
__device__ __forceinline__ uint32_t f2tf32(float f) {
    uint32_t u;
    asm("cvt.rna.tf32.f32 %0, %1;" : "=r"(u) : "f"(f));
    return u;
}
__device__ __forceinline__ void mma8(float c[4], const uint32_t a[4], const uint32_t b[2]) {
    asm volatile(
        "mma.sync.aligned.m16n8k8.row.col.f32.tf32.tf32.f32 "
        "{%0,%1,%2,%3}, {%4,%5,%6,%7}, {%8,%9}, {%0,%1,%2,%3};"
        : "+f"(c[0]), "+f"(c[1]), "+f"(c[2]), "+f"(c[3])
        : "r"(a[0]), "r"(a[1]), "r"(a[2]), "r"(a[3]), "r"(b[0]), "r"(b[1]));
}

// ======================================================================
// 3xTF32 GEMM: C[M,N] = A[M,K] @ W[K,N] + bias.
// BM=128, BN=64, BK=16, 256 threads (8 warps: 4 m-rows x 2 n-cols),
// warp tile 32x32 = 2 m16 x 4 n8 tiles. hi/lo split, 3 mma per tile pair.
// ======================================================================
__global__ void __launch_bounds__(256) gemm3_tf32(
    const float* __restrict__ A, const float* __restrict__ W,
    const float* __restrict__ bias, float* __restrict__ C,
    int M, int N, int K)
{
    __shared__ uint32_t AsHi[16][132], AsLo[16][132];
    __shared__ uint32_t BsHi[16][68],  BsLo[16][68];

    const int tid   = threadIdx.x;
    const int lane  = tid & 31;
    const int wid   = tid >> 5;
    const int warpM = wid & 3;
    const int warpN = wid >> 2;
    const int bm    = blockIdx.y * 128;
    const int bn    = blockIdx.x * 64;

    float acc[2][4][4];
#pragma unroll
    for (int i = 0; i < 2; i++)
#pragma unroll
        for (int j = 0; j < 4; j++)
#pragma unroll
            for (int l = 0; l < 4; l++) acc[i][j][l] = 0.f;

    for (int kt = 0; kt < K; kt += 16) {
        // A tile 128x16 -> As[k][m] (hi/lo)
        {
            int r  = tid >> 1;
            int c0 = (tid & 1) * 8;
            const float* src = A + (size_t)(bm + r) * K + kt + c0;
#pragma unroll
            for (int u = 0; u < 2; u++) {
                float4 v = *(const float4*)(src + u * 4);
                float vv[4] = {v.x, v.y, v.z, v.w};
#pragma unroll
                for (int j = 0; j < 4; j++) {
                    uint32_t hi = f2tf32(vv[j]);
                    float lo = vv[j] - __uint_as_float(hi);
                    AsHi[c0 + u * 4 + j][r] = hi;
                    AsLo[c0 + u * 4 + j][r] = f2tf32(lo);
                }
            }
        }
        // B tile 16x64 -> Bs[k][n] (hi/lo)
        {
            int e  = tid * 4;
            int kr = e >> 6;
            int nc = e & 63;
            float4 v = *(const float4*)(W + (size_t)(kt + kr) * N + bn + nc);
            float vv[4] = {v.x, v.y, v.z, v.w};
#pragma unroll
            for (int j = 0; j < 4; j++) {
                uint32_t hi = f2tf32(vv[j]);
                float lo = vv[j] - __uint_as_float(hi);
                BsHi[kr][nc + j] = hi;
                BsLo[kr][nc + j] = f2tf32(lo);
            }
        }
        __syncthreads();

#pragma unroll
        for (int ks = 0; ks < 2; ks++) {
            const int kb = ks * 8;
            uint32_t aH[2][4], aL[2][4], bH[4][2], bL[4][2];
#pragma unroll
            for (int mt = 0; mt < 2; mt++) {
                int mr = warpM * 32 + mt * 16 + (lane >> 2);
                int kc = kb + (lane & 3);
                aH[mt][0] = AsHi[kc][mr];     aH[mt][1] = AsHi[kc][mr + 8];
                aH[mt][2] = AsHi[kc + 4][mr]; aH[mt][3] = AsHi[kc + 4][mr + 8];
                aL[mt][0] = AsLo[kc][mr];     aL[mt][1] = AsLo[kc][mr + 8];
                aL[mt][2] = AsLo[kc + 4][mr]; aL[mt][3] = AsLo[kc + 4][mr + 8];
            }
#pragma unroll
            for (int nt = 0; nt < 4; nt++) {
                int ncl = warpN * 32 + nt * 8 + (lane >> 2);
                int kc  = kb + (lane & 3);
                bH[nt][0] = BsHi[kc][ncl]; bH[nt][1] = BsHi[kc + 4][ncl];
                bL[nt][0] = BsLo[kc][ncl]; bL[nt][1] = BsLo[kc + 4][ncl];
            }
#pragma unroll
            for (int mt = 0; mt < 2; mt++)
#pragma unroll
                for (int nt = 0; nt < 4; nt++) {
                    mma8(acc[mt][nt], aH[mt], bH[nt]);
                    mma8(acc[mt][nt], aH[mt], bL[nt]);
                    mma8(acc[mt][nt], aL[mt], bH[nt]);
                }
        }
        __syncthreads();
    }

#pragma unroll
    for (int mt = 0; mt < 2; mt++)
#pragma unroll
        for (int nt = 0; nt < 4; nt++) {
            int row = bm + warpM * 32 + mt * 16 + (lane >> 2);
            int col = bn + warpN * 32 + nt * 8 + 2 * (lane & 3);
            float b0 = bias[col], b1 = bias[col + 1];
            float2 o0 = make_float2(acc[mt][nt][0] + b0, acc[mt][nt][1] + b1);
            float2 o1 = make_float2(acc[mt][nt][2] + b0, acc[mt][nt][3] + b1);
            *(float2*)&C[(size_t)row * N + col]       = o0;
            *(float2*)&C[(size_t)(row + 8) * N + col] = o1;
        }
}

// ======================================================================
// 3xTF32 grouped 3x3 conv (implicit GEMM). One group per blockIdx.y.
// K=576 (tap*64+ic). Same tiling as gemm3_tf32 with BN=64.
// ======================================================================
__global__ void __launch_bounds__(256) conv3_tf32(
    const float* __restrict__ Wc, const float* __restrict__ bias)
{
    __shared__ uint32_t AsHi[16][132], AsLo[16][132];
    __shared__ uint32_t BsHi[16][68],  BsLo[16][68];

    const int tid   = threadIdx.x;
    const int lane  = tid & 31;
    const int wid   = tid >> 5;
    const int warpM = wid & 3;
    const int warpN = wid >> 2;
    const int bm    = blockIdx.x * 128;
    const int g     = blockIdx.y;
    const int b     = bm >> 10;

    float acc[2][4][4];
#pragma unroll
    for (int i = 0; i < 2; i++)
#pragma unroll
        for (int j = 0; j < 4; j++)
#pragma unroll
            for (int l = 0; l < 4; l++) acc[i][j][l] = 0.f;

    for (int kt = 0; kt < 576; kt += 16) {
        const int tap = kt >> 6;
        const int dy  = tap / 3 - 1;
        const int dx  = tap % 3 - 1;
        // im2col A tile
        {
            int r  = tid >> 1;
            int c0 = (tid & 1) * 8;
            int ij = (bm + r) & 1023;
            int i0 = ij >> 5, j0 = ij & 31;
            int ii = i0 + dy, jj = j0 + dx;
            bool inb = ((unsigned)ii < 32u) && ((unsigned)jj < 32u);
            int icb = (kt & 63) + c0;   // no wrap within 16-slice
            const float* src = inb
                ? (g_q + (size_t)((b << 10) + (ii << 5) + jj) * NC + g * 64 + icb)
                : (const float*)0;
#pragma unroll
            for (int u = 0; u < 2; u++) {
                float vv[4] = {0.f, 0.f, 0.f, 0.f};
                if (inb) {
                    float4 v = *(const float4*)(src + u * 4);
                    vv[0] = v.x; vv[1] = v.y; vv[2] = v.z; vv[3] = v.w;
                }
#pragma unroll
                for (int j = 0; j < 4; j++) {
                    uint32_t hi = f2tf32(vv[j]);
                    float lo = vv[j] - __uint_as_float(hi);
                    AsHi[c0 + u * 4 + j][r] = hi;
                    AsLo[c0 + u * 4 + j][r] = f2tf32(lo);
                }
            }
        }
        // B tile
        {
            int e  = tid * 4;
            int kr = e >> 6;
            int nc = e & 63;
            float4 v = *(const float4*)(Wc + (size_t)(kt + kr) * NC + g * 64 + nc);
            float vv[4] = {v.x, v.y, v.z, v.w};
#pragma unroll
            for (int j = 0; j < 4; j++) {
                uint32_t hi = f2tf32(vv[j]);
                float lo = vv[j] - __uint_as_float(hi);
                BsHi[kr][nc + j] = hi;
                BsLo[kr][nc + j] = f2tf32(lo);
            }
        }
        __syncthreads();

#pragma unroll
        for (int ks = 0; ks < 2; ks++) {
            const int kb = ks * 8;
            uint32_t aH[2][4], aL[2][4], bH[4][2], bL[4][2];
#pragma unroll
            for (int mt = 0; mt < 2; mt++) {
                int mr = warpM * 32 + mt * 16 + (lane >> 2);
                int kc = kb + (lane & 3);
                aH[mt][0] = AsHi[kc][mr];     aH[mt][1] = AsHi[kc][mr + 8];
                aH[mt][2] = AsHi[kc + 4][mr]; aH[mt][3] = AsHi[kc + 4][mr + 8];
                aL[mt][0] = AsLo[kc][mr];     aL[mt][1] = AsLo[kc][mr + 8];
                aL[mt][2] = AsLo[kc + 4][mr]; aL[mt][3] = AsLo[kc + 4][mr + 8];
            }
#pragma unroll
            for (int nt = 0; nt < 4; nt++) {
                int ncl = warpN * 32 + nt * 8 + (lane >> 2);
                int kc  = kb + (lane & 3);
                bH[nt][0] = BsHi[kc][ncl]; bH[nt][1] = BsHi[kc + 4][ncl];
                bL[nt][0] = BsLo[kc][ncl]; bL[nt][1] = BsLo[kc + 4][ncl];
            }
#pragma unroll
            for (int mt = 0; mt < 2; mt++)
#pragma unroll
                for (int nt = 0; nt < 4; nt++) {
                    mma8(acc[mt][nt], aH[mt], bH[nt]);
                    mma8(acc[mt][nt], aH[mt], bL[nt]);
                    mma8(acc[mt][nt], aL[mt], bH[nt]);
                }
        }
        __syncthreads();
    }

#pragma unroll
    for (int mt = 0; mt < 2; mt++)
#pragma unroll
        for (int nt = 0; nt < 4; nt++) {
            int row = bm + warpM * 32 + mt * 16 + (lane >> 2);
            int col = g * 64 + warpN * 32 + nt * 8 + 2 * (lane & 3);
            float b0 = bias[col], b1 = bias[col + 1];
            float2 o0 = make_float2(acc[mt][nt][0] + b0, acc[mt][nt][1] + b1);
            float2 o1 = make_float2(acc[mt][nt][2] + b0, acc[mt][nt][3] + b1);
            *(float2*)&g_t[(size_t)row * NC + col]       = o0;
            *(float2*)&g_t[(size_t)(row + 8) * NC + col] = o1;
        }
}

// ======================================================================
// LayerNorm -> erf GELU -> 64->2 proj -> tanh*16 + ref -> warp coords.
// ======================================================================
__global__ void __launch_bounds__(128) ln_offset_kernel(
    const float* __restrict__ ln_g, const float* __restrict__ ln_b,
    const float* __restrict__ w_offp)
{
    const int p  = blockIdx.x;
    const int b  = p >> 10;
    const int ij = p & 1023;
    const int i0 = ij >> 5;
    const int j0 = ij & 31;
    const int tid = threadIdx.x;

    __shared__ float ts[NC];
    __shared__ float red[4];

    float lsum = 0.f;
    for (int c = tid; c < NC; c += 128) {
        float v = g_t[(size_t)p * NC + c];
        ts[c] = v;
        lsum += v;
    }
#pragma unroll
    for (int o = 16; o; o >>= 1) lsum += __shfl_xor_sync(0xffffffffu, lsum, o);
    if ((tid & 31) == 0) red[tid >> 5] = lsum;
    __syncthreads();
    const float mu = (red[0] + red[1] + red[2] + red[3]) * (1.f / NC);

    float lsq = 0.f;
    for (int c = tid; c < NC; c += 128) {
        float d = ts[c] - mu;
        lsq += d * d;
    }
#pragma unroll
    for (int o = 16; o; o >>= 1) lsq += __shfl_xor_sync(0xffffffffu, lsq, o);
    __syncthreads();
    if ((tid & 31) == 0) red[tid >> 5] = lsq;
    __syncthreads();
    const float var  = (red[0] + red[1] + red[2] + red[3]) * (1.f / NC);
    const float rstd = rsqrtf(var + 1e-3f);

    for (int c = tid; c < NC; c += 128) {
        float y = (ts[c] - mu) * rstd * ln_g[c] + ln_b[c];
        ts[c] = 0.5f * y * (1.f + erff(y * 0.7071067811865476f));
    }
    __syncthreads();

    if (tid < 12) {
        int g    = tid >> 1;
        int comp = tid & 1;
        float o = 0.f;
        for (int cc = 0; cc < 64; cc++)
            o += ts[g * 64 + cc] * w_offp[cc * 2 + comp];
        float t = tanhf(o) * 16.0f;
        float val = (comp == 0) ? (t + (float)j0) : (t + (float)i0);
        g_warp[(size_t)(((b * NGROUP + g) << 10) + ij) * 2 + (1 - comp)] = val;
    }
}

// ======================================================================
// Bilinear sample (zero border), matches reference formula exactly.
// ======================================================================
__device__ __forceinline__ float fetch_x(const float* __restrict__ x,
                                         int b, int ch, int yy, int xx)
{
    int ri = yy - 1, rj = xx - 1;
    if ((unsigned)ri >= 32u || (unsigned)rj >= 32u) return 0.f;
    return x[(size_t)((b << 10) + (ri << 5) + rj) * NC + ch];
}

__global__ void __launch_bounds__(256) sample_kernel(const float* __restrict__ x)
{
    const int bg   = blockIdx.y;
    const int b    = bg / NGROUP;
    const int g    = bg % NGROUP;
    const int qidx = blockIdx.x * 4 + (threadIdx.x >> 6);
    const int cc   = threadIdx.x & 63;
    const int ch   = g * 64 + cc;

    const float wx = g_warp[(size_t)((bg << 10) + qidx) * 2 + 0];
    const float wy = g_warp[(size_t)((bg << 10) + qidx) * 2 + 1];

    const float xq = wx + 1.f;
    const float yq = wy + 1.f;
    float y0f = fminf(fmaxf(floorf(yq), 0.f), 32.f);
    float x0f = fminf(fmaxf(floorf(xq), 0.f), 32.f);
    float ay  = fminf(fmaxf(yq - y0f, 0.f), 1.f);
    float ax  = fminf(fmaxf(xq - x0f, 0.f), 1.f);
    int y0 = (int)y0f, x0 = (int)x0f;

    float tl = fetch_x(x, b, ch, y0,     x0);
    float tr = fetch_x(x, b, ch, y0,     x0 + 1);
    float bl = fetch_x(x, b, ch, y0 + 1, x0);
    float br = fetch_x(x, b, ch, y0 + 1, x0 + 1);

    float top = tl + ax * (tr - tl);
    float bot = bl + ax * (br - bl);
    g_xs[(size_t)((b << 10) + qidx) * NC + ch] = top + ay * (bot - top);
}

// ======================================================================
// Flash attention, 1xTF32 mma. Block = 128 queries x (b,h); 8 warps,
// warp owns 16 query rows end-to-end (no cross-warp reductions).
// Per 64-key chunk: S = Q K^T (mma), online softmax in C-fragments,
// P -> smem (tf32, A-frag layout), O += P V (mma).
// ======================================================================
#define KPAD 36
#define PPAD 66
__global__ void __launch_bounds__(256) attn_tf32()
{
    const int qt  = blockIdx.x;     // 0..7
    const int h   = blockIdx.y;
    const int b   = blockIdx.z;
    const int tid = threadIdx.x;
    const int lane = tid & 31;
    const int w    = tid >> 5;
    const int qrow0 = qt * 128 + w * 16;

    extern __shared__ uint32_t dsm[];
    uint32_t* Ks = dsm;                  // 64 x KPAD
    uint32_t* Vs = Ks + 64 * KPAD;       // 64 x KPAD
    uint32_t* Ps = Vs + 64 * KPAD;       // 8 x 16 x PPAD

    // Q fragments (scale folded in), loaded once
    const float scale = 0.17677669529663687f;
    uint32_t qf[4][4];
    {
        size_t r0 = (size_t)((b << 10) + qrow0 + (lane >> 2));
#pragma unroll
        for (int ks = 0; ks < 4; ks++) {
            int c = h * HC + ks * 8 + (lane & 3);
            qf[ks][0] = f2tf32(g_q[r0 * NC + c] * scale);
            qf[ks][1] = f2tf32(g_q[(r0 + 8) * NC + c] * scale);
            qf[ks][2] = f2tf32(g_q[r0 * NC + c + 4] * scale);
            qf[ks][3] = f2tf32(g_q[(r0 + 8) * NC + c + 4] * scale);
        }
    }

    float m0 = -1e30f, m1 = -1e30f, l0 = 0.f, l1 = 0.f;
    float oacc[4][4];
#pragma unroll
    for (int i = 0; i < 4; i++)
#pragma unroll
        for (int j = 0; j < 4; j++) oacc[i][j] = 0.f;

    for (int kc = 0; kc < 1024; kc += 64) {
        __syncthreads();
        // load K, V chunk (coalesced float4, convert tf32)
        {
            int kk = tid >> 2;
            int cc = (tid & 3) * 8;
            const float* kp = g_k + (size_t)((b << 10) + kc + kk) * NC + h * HC + cc;
            const float* vp = g_v + (size_t)((b << 10) + kc + kk) * NC + h * HC + cc;
#pragma unroll
            for (int u = 0; u < 2; u++) {
                float4 kv = *(const float4*)(kp + u * 4);
                float4 vv = *(const float4*)(vp + u * 4);
                Ks[kk * KPAD + cc + u * 4 + 0] = f2tf32(kv.x);
                Ks[kk * KPAD + cc + u * 4 + 1] = f2tf32(kv.y);
                Ks[kk * KPAD + cc + u * 4 + 2] = f2tf32(kv.z);
                Ks[kk * KPAD + cc + u * 4 + 3] = f2tf32(kv.w);
                Vs[kk * KPAD + cc + u * 4 + 0] = f2tf32(vv.x);
                Vs[kk * KPAD + cc + u * 4 + 1] = f2tf32(vv.y);
                Vs[kk * KPAD + cc + u * 4 + 2] = f2tf32(vv.z);
                Vs[kk * KPAD + cc + u * 4 + 3] = f2tf32(vv.w);
            }
        }
        __syncthreads();

        // S = Q K^T (16 x 64)
        float S[8][4];
#pragma unroll
        for (int nt = 0; nt < 8; nt++) {
#pragma unroll
            for (int j = 0; j < 4; j++) S[nt][j] = 0.f;
            int key = nt * 8 + (lane >> 2);
#pragma unroll
            for (int ks = 0; ks < 4; ks++) {
                uint32_t bf[2];
                int ch = ks * 8 + (lane & 3);
                bf[0] = Ks[key * KPAD + ch];
                bf[1] = Ks[key * KPAD + ch + 4];
                mma8(S[nt], qf[ks], bf);
            }
        }

        // online softmax (rows lane>>2 and lane>>2 + 8)
        float cm0 = -1e30f, cm1 = -1e30f;
#pragma unroll
        for (int nt = 0; nt < 8; nt++) {
            cm0 = fmaxf(cm0, fmaxf(S[nt][0], S[nt][1]));
            cm1 = fmaxf(cm1, fmaxf(S[nt][2], S[nt][3]));
        }
        cm0 = fmaxf(cm0, __shfl_xor_sync(0xffffffffu, cm0, 1));
        cm0 = fmaxf(cm0, __shfl_xor_sync(0xffffffffu, cm0, 2));
        cm1 = fmaxf(cm1, __shfl_xor_sync(0xffffffffu, cm1, 1));
        cm1 = fmaxf(cm1, __shfl_xor_sync(0xffffffffu, cm1, 2));
        float nm0 = fmaxf(m0, cm0), nm1 = fmaxf(m1, cm1);
        float a0 = __expf(m0 - nm0), a1 = __expf(m1 - nm1);
        float s0 = 0.f, s1 = 0.f;
#pragma unroll
        for (int nt = 0; nt < 8; nt++) {
            S[nt][0] = __expf(S[nt][0] - nm0); s0 += S[nt][0];
            S[nt][1] = __expf(S[nt][1] - nm0); s0 += S[nt][1];
            S[nt][2] = __expf(S[nt][2] - nm1); s1 += S[nt][2];
            S[nt][3] = __expf(S[nt][3] - nm1); s1 += S[nt][3];
        }
        s0 += __shfl_xor_sync(0xffffffffu, s0, 1);
        s0 += __shfl_xor_sync(0xffffffffu, s0, 2);
        s1 += __shfl_xor_sync(0xffffffffu, s1, 1);
        s1 += __shfl_xor_sync(0xffffffffu, s1, 2);
        l0 = l0 * a0 + s0; l1 = l1 * a1 + s1;
        m0 = nm0; m1 = nm1;
#pragma unroll
        for (int ct = 0; ct < 4; ct++) {
            oacc[ct][0] *= a0; oacc[ct][1] *= a0;
            oacc[ct][2] *= a1; oacc[ct][3] *= a1;
        }

        // P -> smem (tf32) in A-frag friendly layout
        uint32_t* Pw = Ps + w * 16 * PPAD;
        {
            int r = lane >> 2;
#pragma unroll
            for (int nt = 0; nt < 8; nt++) {
                int cl = nt * 8 + 2 * (lane & 3);
                Pw[r * PPAD + cl]           = f2tf32(S[nt][0]);
                Pw[r * PPAD + cl + 1]       = f2tf32(S[nt][1]);
                Pw[(r + 8) * PPAD + cl]     = f2tf32(S[nt][2]);
                Pw[(r + 8) * PPAD + cl + 1] = f2tf32(S[nt][3]);
            }
        }
        __syncwarp();

        // O += P @ V
#pragma unroll
        for (int ks = 0; ks < 8; ks++) {
            uint32_t pf[4];
            int r = lane >> 2, c = ks * 8 + (lane & 3);
            pf[0] = Pw[r * PPAD + c];       pf[1] = Pw[(r + 8) * PPAD + c];
            pf[2] = Pw[r * PPAD + c + 4];   pf[3] = Pw[(r + 8) * PPAD + c + 4];
#pragma unroll
            for (int ct = 0; ct < 4; ct++) {
                uint32_t bf[2];
                int key = ks * 8 + (lane & 3);
                int ch  = ct * 8 + (lane >> 2);
                bf[0] = Vs[key * KPAD + ch];
                bf[1] = Vs[(key + 4) * KPAD + ch];
                mma8(oacc[ct], pf, bf);
            }
        }
    }

    // epilogue
    float il0 = 1.f / l0, il1 = 1.f / l1;
    size_t row = (size_t)((b << 10) + qrow0 + (lane >> 2));
#pragma unroll
    for (int ct = 0; ct < 4; ct++) {
        int col = h * HC + ct * 8 + 2 * (lane & 3);
        float2 o0 = make_float2(oacc[ct][0] * il0, oacc[ct][1] * il0);
        float2 o1 = make_float2(oacc[ct][2] * il1, oacc[ct][3] * il1);
        *(float2*)&g_ao[row * NC + col]       = o0;
        *(float2*)&g_ao[(row + 8) * NC + col] = o1;
    }
}

// ======================================================================
// Host launcher
// ======================================================================
extern "C" void kernel_launch(void* const* d_in, const int* in_sizes, int n_in,
                              void* d_out, int out_size)
{
    (void)in_sizes; (void)n_in; (void)out_size;
    const float* x      = (const float*)d_in[0];
    const float* w_q    = (const float*)d_in[1];
    const float* b_q    = (const float*)d_in[2];
    const float* w_off0 = (const float*)d_in[3];
    const float* b_off0 = (const float*)d_in[4];
    const float* ln_g   = (const float*)d_in[5];
    const float* ln_b   = (const float*)d_in[6];
    const float* w_offp = (const float*)d_in[7];
    const float* w_k    = (const float*)d_in[8];
    const float* b_k    = (const float*)d_in[9];
    const float* w_v    = (const float*)d_in[10];
    const float* b_v    = (const float*)d_in[11];
    const float* w_o    = (const float*)d_in[12];
    const float* b_o    = (const float*)d_in[13];
    float* out = (float*)d_out;

    float *pq, *pxs, *pk, *pv, *pao;
    cudaGetSymbolAddress((void**)&pq,  g_q);
    cudaGetSymbolAddress((void**)&pxs, g_xs);
    cudaGetSymbolAddress((void**)&pk,  g_k);
    cudaGetSymbolAddress((void**)&pv,  g_v);
    cudaGetSymbolAddress((void**)&pao, g_ao);

    const dim3 gemm_grid(NC / 64, MTOT / 128);   // (6, 64)

    // 1) q = x @ w_q + b_q   (3xTF32)
    gemm3_tf32<<<gemm_grid, 256>>>(x, w_q, b_q, pq, MTOT, NC, NC);
    // 2) grouped conv -> g_t (3xTF32)
    conv3_tf32<<<dim3(MTOT / 128, NGROUP), 256>>>(w_off0, b_off0);
    // 3) LN + GELU + offset proj + warp coords (fp32)
    ln_offset_kernel<<<MTOT, 128>>>(ln_g, ln_b, w_offp);
    // 4) bilinear sampling (fp32)
    sample_kernel<<<dim3(256, BATCH * NGROUP), 256>>>(x);
    // 5) k, v projections (3xTF32)
    gemm3_tf32<<<gemm_grid, 256>>>(pxs, w_k, b_k, pk, MTOT, NC, NC);
    gemm3_tf32<<<gemm_grid, 256>>>(pxs, w_v, b_v, pv, MTOT, NC, NC);
    // 6) flash attention (1xTF32)
    const int attn_smem = (64 * KPAD * 2 + 8 * 16 * PPAD) * (int)sizeof(uint32_t);
    cudaFuncSetAttribute(attn_tf32, cudaFuncAttributeMaxDynamicSharedMemorySize, attn_smem);
    attn_tf32<<<dim3(8, NHEAD, BATCH), 256, attn_smem>>>();
    // 7) y = attn_out @ w_o + b_o (3xTF32)
    gemm3_tf32<<<gemm_grid, 256>>>(pao, w_o, b_o, out, MTOT, NC, NC);
}

// round 7
// speedup vs baseline: 2.4126x; 1.2686x over previous
#include <cuda_runtime.h>
#include <math.h>
#include <stdint.h>

// Problem constants
#define BATCH   8
#define NC      384
#define NGROUP  6
#define NHEAD   12
#define HC      32
#define GC      64
#define NPOS    1024
#define MTOT    (BATCH * NPOS)  // 8192

// ---------------- device scratch ----------
__device__ float g_q  [MTOT * NC];
__device__ float g_t  [MTOT * NC];
__device__ float g_warp[BATCH * NGROUP * NPOS * 2];
__device__ float g_xs [MTOT * NC];
__device__ float g_k  [MTOT * NC];
__device__ float g_v  [MTOT * NC];
__device__ float g_ao [MTOT * NC];

// ---------------- tf32 mma helpers ----------
__device__ __forceinline__ uint32_t f2tf32(float f) {
    uint32_t u;
    asm("cvt.rna.tf32.f32 %0, %1;" : "=r"(u) : "f"(f));
    return u;
}
__device__ __forceinline__ void mma8(float c[4], const uint32_t a[4], const uint32_t b[2]) {
    asm volatile(
        "mma.sync.aligned.m16n8k8.row.col.f32.tf32.tf32.f32 "
        "{%0,%1,%2,%3}, {%4,%5,%6,%7}, {%8,%9}, {%0,%1,%2,%3};"
        : "+f"(c[0]), "+f"(c[1]), "+f"(c[2]), "+f"(c[3])
        : "r"(a[0]), "r"(a[1]), "r"(a[2]), "r"(a[3]), "r"(b[0]), "r"(b[1]));
}

// ======================================================================
// 3xTF32 GEMM (full fp32 accuracy): C = A @ W + bias.
// BM=128, BN=64, BK=16, 256 threads, warp tile 32x32.
// Used for q (offset-branch sensitivity) and the final o projection.
// ======================================================================
__global__ void __launch_bounds__(256) gemm3_tf32(
    const float* __restrict__ A, const float* __restrict__ W,
    const float* __restrict__ bias, float* __restrict__ C,
    int M, int N, int K)
{
    __shared__ uint32_t AsHi[16][132], AsLo[16][132];
    __shared__ uint32_t BsHi[16][68],  BsLo[16][68];

    const int tid   = threadIdx.x;
    const int lane  = tid & 31;
    const int wid   = tid >> 5;
    const int warpM = wid & 3;
    const int warpN = wid >> 2;
    const int bm    = blockIdx.y * 128;
    const int bn    = blockIdx.x * 64;

    float acc[2][4][4];
#pragma unroll
    for (int i = 0; i < 2; i++)
#pragma unroll
        for (int j = 0; j < 4; j++)
#pragma unroll
            for (int l = 0; l < 4; l++) acc[i][j][l] = 0.f;

    for (int kt = 0; kt < K; kt += 16) {
        {
            int r  = tid >> 1;
            int c0 = (tid & 1) * 8;
            const float* src = A + (size_t)(bm + r) * K + kt + c0;
#pragma unroll
            for (int u = 0; u < 2; u++) {
                float4 v = *(const float4*)(src + u * 4);
                float vv[4] = {v.x, v.y, v.z, v.w};
#pragma unroll
                for (int j = 0; j < 4; j++) {
                    uint32_t hi = f2tf32(vv[j]);
                    float lo = vv[j] - __uint_as_float(hi);
                    AsHi[c0 + u * 4 + j][r] = hi;
                    AsLo[c0 + u * 4 + j][r] = f2tf32(lo);
                }
            }
        }
        {
            int e  = tid * 4;
            int kr = e >> 6;
            int nc = e & 63;
            float4 v = *(const float4*)(W + (size_t)(kt + kr) * N + bn + nc);
            float vv[4] = {v.x, v.y, v.z, v.w};
#pragma unroll
            for (int j = 0; j < 4; j++) {
                uint32_t hi = f2tf32(vv[j]);
                float lo = vv[j] - __uint_as_float(hi);
                BsHi[kr][nc + j] = hi;
                BsLo[kr][nc + j] = f2tf32(lo);
            }
        }
        __syncthreads();

#pragma unroll
        for (int ks = 0; ks < 2; ks++) {
            const int kb = ks * 8;
            uint32_t aH[2][4], aL[2][4], bH[4][2], bL[4][2];
#pragma unroll
            for (int mt = 0; mt < 2; mt++) {
                int mr = warpM * 32 + mt * 16 + (lane >> 2);
                int kc = kb + (lane & 3);
                aH[mt][0] = AsHi[kc][mr];     aH[mt][1] = AsHi[kc][mr + 8];
                aH[mt][2] = AsHi[kc + 4][mr]; aH[mt][3] = AsHi[kc + 4][mr + 8];
                aL[mt][0] = AsLo[kc][mr];     aL[mt][1] = AsLo[kc][mr + 8];
                aL[mt][2] = AsLo[kc + 4][mr]; aL[mt][3] = AsLo[kc + 4][mr + 8];
            }
#pragma unroll
            for (int nt = 0; nt < 4; nt++) {
                int ncl = warpN * 32 + nt * 8 + (lane >> 2);
                int kc  = kb + (lane & 3);
                bH[nt][0] = BsHi[kc][ncl]; bH[nt][1] = BsHi[kc + 4][ncl];
                bL[nt][0] = BsLo[kc][ncl]; bL[nt][1] = BsLo[kc + 4][ncl];
            }
#pragma unroll
            for (int mt = 0; mt < 2; mt++)
#pragma unroll
                for (int nt = 0; nt < 4; nt++) {
                    mma8(acc[mt][nt], aH[mt], bH[nt]);
                    mma8(acc[mt][nt], aH[mt], bL[nt]);
                    mma8(acc[mt][nt], aL[mt], bH[nt]);
                }
        }
        __syncthreads();
    }

#pragma unroll
    for (int mt = 0; mt < 2; mt++)
#pragma unroll
        for (int nt = 0; nt < 4; nt++) {
            int row = bm + warpM * 32 + mt * 16 + (lane >> 2);
            int col = bn + warpN * 32 + nt * 8 + 2 * (lane & 3);
            float b0 = bias[col], b1 = bias[col + 1];
            float2 o0 = make_float2(acc[mt][nt][0] + b0, acc[mt][nt][1] + b1);
            float2 o1 = make_float2(acc[mt][nt][2] + b0, acc[mt][nt][3] + b1);
            *(float2*)&C[(size_t)row * N + col]       = o0;
            *(float2*)&C[(size_t)(row + 8) * N + col] = o1;
        }
}

// ======================================================================
// Fused 1xTF32 K+V projection: k = xs@Wk+bk, v = xs@Wv+bv.
// Shares the A tile (loaded+converted once) between both outputs.
// ======================================================================
__global__ void __launch_bounds__(256) kv_gemm1_tf32(
    const float* __restrict__ A,
    const float* __restrict__ Wk, const float* __restrict__ bk,
    const float* __restrict__ Wv, const float* __restrict__ bv)
{
    __shared__ uint32_t As [16][132];
    __shared__ uint32_t BsK[16][68];
    __shared__ uint32_t BsV[16][68];

    const int tid   = threadIdx.x;
    const int lane  = tid & 31;
    const int wid   = tid >> 5;
    const int warpM = wid & 3;
    const int warpN = wid >> 2;
    const int bm    = blockIdx.y * 128;
    const int bn    = blockIdx.x * 64;

    float accK[2][4][4], accV[2][4][4];
#pragma unroll
    for (int i = 0; i < 2; i++)
#pragma unroll
        for (int j = 0; j < 4; j++)
#pragma unroll
            for (int l = 0; l < 4; l++) { accK[i][j][l] = 0.f; accV[i][j][l] = 0.f; }

    for (int kt = 0; kt < NC; kt += 16) {
        {
            int r  = tid >> 1;
            int c0 = (tid & 1) * 8;
            const float* src = A + (size_t)(bm + r) * NC + kt + c0;
#pragma unroll
            for (int u = 0; u < 2; u++) {
                float4 v = *(const float4*)(src + u * 4);
                As[c0 + u * 4 + 0][r] = f2tf32(v.x);
                As[c0 + u * 4 + 1][r] = f2tf32(v.y);
                As[c0 + u * 4 + 2][r] = f2tf32(v.z);
                As[c0 + u * 4 + 3][r] = f2tf32(v.w);
            }
        }
        {
            int e  = tid * 4;
            int kr = e >> 6;
            int nc = e & 63;
            float4 vk = *(const float4*)(Wk + (size_t)(kt + kr) * NC + bn + nc);
            float4 vv = *(const float4*)(Wv + (size_t)(kt + kr) * NC + bn + nc);
            BsK[kr][nc + 0] = f2tf32(vk.x); BsK[kr][nc + 1] = f2tf32(vk.y);
            BsK[kr][nc + 2] = f2tf32(vk.z); BsK[kr][nc + 3] = f2tf32(vk.w);
            BsV[kr][nc + 0] = f2tf32(vv.x); BsV[kr][nc + 1] = f2tf32(vv.y);
            BsV[kr][nc + 2] = f2tf32(vv.z); BsV[kr][nc + 3] = f2tf32(vv.w);
        }
        __syncthreads();

#pragma unroll
        for (int ks = 0; ks < 2; ks++) {
            const int kb = ks * 8;
            uint32_t aF[2][4], bK[4][2], bV[4][2];
#pragma unroll
            for (int mt = 0; mt < 2; mt++) {
                int mr = warpM * 32 + mt * 16 + (lane >> 2);
                int kc = kb + (lane & 3);
                aF[mt][0] = As[kc][mr];     aF[mt][1] = As[kc][mr + 8];
                aF[mt][2] = As[kc + 4][mr]; aF[mt][3] = As[kc + 4][mr + 8];
            }
#pragma unroll
            for (int nt = 0; nt < 4; nt++) {
                int ncl = warpN * 32 + nt * 8 + (lane >> 2);
                int kc  = kb + (lane & 3);
                bK[nt][0] = BsK[kc][ncl]; bK[nt][1] = BsK[kc + 4][ncl];
                bV[nt][0] = BsV[kc][ncl]; bV[nt][1] = BsV[kc + 4][ncl];
            }
#pragma unroll
            for (int mt = 0; mt < 2; mt++)
#pragma unroll
                for (int nt = 0; nt < 4; nt++) {
                    mma8(accK[mt][nt], aF[mt], bK[nt]);
                    mma8(accV[mt][nt], aF[mt], bV[nt]);
                }
        }
        __syncthreads();
    }

#pragma unroll
    for (int mt = 0; mt < 2; mt++)
#pragma unroll
        for (int nt = 0; nt < 4; nt++) {
            int row = bm + warpM * 32 + mt * 16 + (lane >> 2);
            int col = bn + warpN * 32 + nt * 8 + 2 * (lane & 3);
            float k0 = bk[col], k1 = bk[col + 1];
            float v0 = bv[col], v1 = bv[col + 1];
            *(float2*)&g_k[(size_t)row * NC + col] =
                make_float2(accK[mt][nt][0] + k0, accK[mt][nt][1] + k1);
            *(float2*)&g_k[(size_t)(row + 8) * NC + col] =
                make_float2(accK[mt][nt][2] + k0, accK[mt][nt][3] + k1);
            *(float2*)&g_v[(size_t)row * NC + col] =
                make_float2(accV[mt][nt][0] + v0, accV[mt][nt][1] + v1);
            *(float2*)&g_v[(size_t)(row + 8) * NC + col] =
                make_float2(accV[mt][nt][2] + v0, accV[mt][nt][3] + v1);
        }
}

// ======================================================================
// 1xTF32 grouped 3x3 conv (implicit GEMM). Coordinate errors induced
// (~6e-4 px) are i.i.d. across keys and average out through softmax.
// ======================================================================
__global__ void __launch_bounds__(256) conv1_tf32(
    const float* __restrict__ Wc, const float* __restrict__ bias)
{
    __shared__ uint32_t As[16][132];
    __shared__ uint32_t Bs[16][68];

    const int tid   = threadIdx.x;
    const int lane  = tid & 31;
    const int wid   = tid >> 5;
    const int warpM = wid & 3;
    const int warpN = wid >> 2;
    const int bm    = blockIdx.x * 128;
    const int g     = blockIdx.y;
    const int b     = bm >> 10;

    float acc[2][4][4];
#pragma unroll
    for (int i = 0; i < 2; i++)
#pragma unroll
        for (int j = 0; j < 4; j++)
#pragma unroll
            for (int l = 0; l < 4; l++) acc[i][j][l] = 0.f;

    for (int kt = 0; kt < 576; kt += 16) {
        const int tap = kt >> 6;
        const int dy  = tap / 3 - 1;
        const int dx  = tap % 3 - 1;
        {
            int r  = tid >> 1;
            int c0 = (tid & 1) * 8;
            int ij = (bm + r) & 1023;
            int i0 = ij >> 5, j0 = ij & 31;
            int ii = i0 + dy, jj = j0 + dx;
            bool inb = ((unsigned)ii < 32u) && ((unsigned)jj < 32u);
            int icb = (kt & 63) + c0;
            const float* src = inb
                ? (g_q + (size_t)((b << 10) + (ii << 5) + jj) * NC + g * 64 + icb)
                : (const float*)0;
#pragma unroll
            for (int u = 0; u < 2; u++) {
                float vv[4] = {0.f, 0.f, 0.f, 0.f};
                if (inb) {
                    float4 v = *(const float4*)(src + u * 4);
                    vv[0] = v.x; vv[1] = v.y; vv[2] = v.z; vv[3] = v.w;
                }
#pragma unroll
                for (int j = 0; j < 4; j++)
                    As[c0 + u * 4 + j][r] = f2tf32(vv[j]);
            }
        }
        {
            int e  = tid * 4;
            int kr = e >> 6;
            int nc = e & 63;
            float4 v = *(const float4*)(Wc + (size_t)(kt + kr) * NC + g * 64 + nc);
            Bs[kr][nc + 0] = f2tf32(v.x); Bs[kr][nc + 1] = f2tf32(v.y);
            Bs[kr][nc + 2] = f2tf32(v.z); Bs[kr][nc + 3] = f2tf32(v.w);
        }
        __syncthreads();

#pragma unroll
        for (int ks = 0; ks < 2; ks++) {
            const int kb = ks * 8;
            uint32_t aF[2][4], bF[4][2];
#pragma unroll
            for (int mt = 0; mt < 2; mt++) {
                int mr = warpM * 32 + mt * 16 + (lane >> 2);
                int kc = kb + (lane & 3);
                aF[mt][0] = As[kc][mr];     aF[mt][1] = As[kc][mr + 8];
                aF[mt][2] = As[kc + 4][mr]; aF[mt][3] = As[kc + 4][mr + 8];
            }
#pragma unroll
            for (int nt = 0; nt < 4; nt++) {
                int ncl = warpN * 32 + nt * 8 + (lane >> 2);
                int kc  = kb + (lane & 3);
                bF[nt][0] = Bs[kc][ncl]; bF[nt][1] = Bs[kc + 4][ncl];
            }
#pragma unroll
            for (int mt = 0; mt < 2; mt++)
#pragma unroll
                for (int nt = 0; nt < 4; nt++)
                    mma8(acc[mt][nt], aF[mt], bF[nt]);
        }
        __syncthreads();
    }

#pragma unroll
    for (int mt = 0; mt < 2; mt++)
#pragma unroll
        for (int nt = 0; nt < 4; nt++) {
            int row = bm + warpM * 32 + mt * 16 + (lane >> 2);
            int col = g * 64 + warpN * 32 + nt * 8 + 2 * (lane & 3);
            float b0 = bias[col], b1 = bias[col + 1];
            *(float2*)&g_t[(size_t)row * NC + col] =
                make_float2(acc[mt][nt][0] + b0, acc[mt][nt][1] + b1);
            *(float2*)&g_t[(size_t)(row + 8) * NC + col] =
                make_float2(acc[mt][nt][2] + b0, acc[mt][nt][3] + b1);
        }
}

// ======================================================================
// LayerNorm -> erf GELU -> 64->2 proj -> tanh*16 + ref -> warp coords.
// ======================================================================
__global__ void __launch_bounds__(128) ln_offset_kernel(
    const float* __restrict__ ln_g, const float* __restrict__ ln_b,
    const float* __restrict__ w_offp)
{
    const int p  = blockIdx.x;
    const int b  = p >> 10;
    const int ij = p & 1023;
    const int i0 = ij >> 5;
    const int j0 = ij & 31;
    const int tid = threadIdx.x;

    __shared__ float ts[NC];
    __shared__ float red[4];

    float lsum = 0.f;
    for (int c = tid; c < NC; c += 128) {
        float v = g_t[(size_t)p * NC + c];
        ts[c] = v;
        lsum += v;
    }
#pragma unroll
    for (int o = 16; o; o >>= 1) lsum += __shfl_xor_sync(0xffffffffu, lsum, o);
    if ((tid & 31) == 0) red[tid >> 5] = lsum;
    __syncthreads();
    const float mu = (red[0] + red[1] + red[2] + red[3]) * (1.f / NC);

    float lsq = 0.f;
    for (int c = tid; c < NC; c += 128) {
        float d = ts[c] - mu;
        lsq += d * d;
    }
#pragma unroll
    for (int o = 16; o; o >>= 1) lsq += __shfl_xor_sync(0xffffffffu, lsq, o);
    __syncthreads();
    if ((tid & 31) == 0) red[tid >> 5] = lsq;
    __syncthreads();
    const float var  = (red[0] + red[1] + red[2] + red[3]) * (1.f / NC);
    const float rstd = rsqrtf(var + 1e-3f);

    for (int c = tid; c < NC; c += 128) {
        float y = (ts[c] - mu) * rstd * ln_g[c] + ln_b[c];
        ts[c] = 0.5f * y * (1.f + erff(y * 0.7071067811865476f));
    }
    __syncthreads();

    if (tid < 12) {
        int g    = tid >> 1;
        int comp = tid & 1;
        float o = 0.f;
        for (int cc = 0; cc < 64; cc++)
            o += ts[g * 64 + cc] * w_offp[cc * 2 + comp];
        float t = tanhf(o) * 16.0f;
        float val = (comp == 0) ? (t + (float)j0) : (t + (float)i0);
        g_warp[(size_t)(((b * NGROUP + g) << 10) + ij) * 2 + (1 - comp)] = val;
    }
}

// ======================================================================
// Bilinear sample (zero border), matches reference formula exactly.
// ======================================================================
__device__ __forceinline__ float fetch_x(const float* __restrict__ x,
                                         int b, int ch, int yy, int xx)
{
    int ri = yy - 1, rj = xx - 1;
    if ((unsigned)ri >= 32u || (unsigned)rj >= 32u) return 0.f;
    return x[(size_t)((b << 10) + (ri << 5) + rj) * NC + ch];
}

__global__ void __launch_bounds__(256) sample_kernel(const float* __restrict__ x)
{
    const int bg   = blockIdx.y;
    const int b    = bg / NGROUP;
    const int g    = bg % NGROUP;
    const int qidx = blockIdx.x * 4 + (threadIdx.x >> 6);
    const int cc   = threadIdx.x & 63;
    const int ch   = g * 64 + cc;

    const float wx = g_warp[(size_t)((bg << 10) + qidx) * 2 + 0];
    const float wy = g_warp[(size_t)((bg << 10) + qidx) * 2 + 1];

    const float xq = wx + 1.f;
    const float yq = wy + 1.f;
    float y0f = fminf(fmaxf(floorf(yq), 0.f), 32.f);
    float x0f = fminf(fmaxf(floorf(xq), 0.f), 32.f);
    float ay  = fminf(fmaxf(yq - y0f, 0.f), 1.f);
    float ax  = fminf(fmaxf(xq - x0f, 0.f), 1.f);
    int y0 = (int)y0f, x0 = (int)x0f;

    float tl = fetch_x(x, b, ch, y0,     x0);
    float tr = fetch_x(x, b, ch, y0,     x0 + 1);
    float bl = fetch_x(x, b, ch, y0 + 1, x0);
    float br = fetch_x(x, b, ch, y0 + 1, x0 + 1);

    float top = tl + ax * (tr - tl);
    float bot = bl + ax * (br - bl);
    g_xs[(size_t)((b << 10) + qidx) * NC + ch] = top + ay * (bot - top);
}

// ======================================================================
// Flash attention, 1xTF32 mma (unchanged from round 6).
// ======================================================================
#define KPAD 36
#define PPAD 66
__global__ void __launch_bounds__(256) attn_tf32()
{
    const int qt  = blockIdx.x;
    const int h   = blockIdx.y;
    const int b   = blockIdx.z;
    const int tid = threadIdx.x;
    const int lane = tid & 31;
    const int w    = tid >> 5;
    const int qrow0 = qt * 128 + w * 16;

    extern __shared__ uint32_t dsm[];
    uint32_t* Ks = dsm;
    uint32_t* Vs = Ks + 64 * KPAD;
    uint32_t* Ps = Vs + 64 * KPAD;

    const float scale = 0.17677669529663687f;
    uint32_t qf[4][4];
    {
        size_t r0 = (size_t)((b << 10) + qrow0 + (lane >> 2));
#pragma unroll
        for (int ks = 0; ks < 4; ks++) {
            int c = h * HC + ks * 8 + (lane & 3);
            qf[ks][0] = f2tf32(g_q[r0 * NC + c] * scale);
            qf[ks][1] = f2tf32(g_q[(r0 + 8) * NC + c] * scale);
            qf[ks][2] = f2tf32(g_q[r0 * NC + c + 4] * scale);
            qf[ks][3] = f2tf32(g_q[(r0 + 8) * NC + c + 4] * scale);
        }
    }

    float m0 = -1e30f, m1 = -1e30f, l0 = 0.f, l1 = 0.f;
    float oacc[4][4];
#pragma unroll
    for (int i = 0; i < 4; i++)
#pragma unroll
        for (int j = 0; j < 4; j++) oacc[i][j] = 0.f;

    for (int kc = 0; kc < 1024; kc += 64) {
        __syncthreads();
        {
            int kk = tid >> 2;
            int cc = (tid & 3) * 8;
            const float* kp = g_k + (size_t)((b << 10) + kc + kk) * NC + h * HC + cc;
            const float* vp = g_v + (size_t)((b << 10) + kc + kk) * NC + h * HC + cc;
#pragma unroll
            for (int u = 0; u < 2; u++) {
                float4 kv = *(const float4*)(kp + u * 4);
                float4 vv = *(const float4*)(vp + u * 4);
                Ks[kk * KPAD + cc + u * 4 + 0] = f2tf32(kv.x);
                Ks[kk * KPAD + cc + u * 4 + 1] = f2tf32(kv.y);
                Ks[kk * KPAD + cc + u * 4 + 2] = f2tf32(kv.z);
                Ks[kk * KPAD + cc + u * 4 + 3] = f2tf32(kv.w);
                Vs[kk * KPAD + cc + u * 4 + 0] = f2tf32(vv.x);
                Vs[kk * KPAD + cc + u * 4 + 1] = f2tf32(vv.y);
                Vs[kk * KPAD + cc + u * 4 + 2] = f2tf32(vv.z);
                Vs[kk * KPAD + cc + u * 4 + 3] = f2tf32(vv.w);
            }
        }
        __syncthreads();

        float S[8][4];
#pragma unroll
        for (int nt = 0; nt < 8; nt++) {
#pragma unroll
            for (int j = 0; j < 4; j++) S[nt][j] = 0.f;
            int key = nt * 8 + (lane >> 2);
#pragma unroll
            for (int ks = 0; ks < 4; ks++) {
                uint32_t bf[2];
                int ch = ks * 8 + (lane & 3);
                bf[0] = Ks[key * KPAD + ch];
                bf[1] = Ks[key * KPAD + ch + 4];
                mma8(S[nt], qf[ks], bf);
            }
        }

        float cm0 = -1e30f, cm1 = -1e30f;
#pragma unroll
        for (int nt = 0; nt < 8; nt++) {
            cm0 = fmaxf(cm0, fmaxf(S[nt][0], S[nt][1]));
            cm1 = fmaxf(cm1, fmaxf(S[nt][2], S[nt][3]));
        }
        cm0 = fmaxf(cm0, __shfl_xor_sync(0xffffffffu, cm0, 1));
        cm0 = fmaxf(cm0, __shfl_xor_sync(0xffffffffu, cm0, 2));
        cm1 = fmaxf(cm1, __shfl_xor_sync(0xffffffffu, cm1, 1));
        cm1 = fmaxf(cm1, __shfl_xor_sync(0xffffffffu, cm1, 2));
        float nm0 = fmaxf(m0, cm0), nm1 = fmaxf(m1, cm1);
        float a0 = __expf(m0 - nm0), a1 = __expf(m1 - nm1);
        float s0 = 0.f, s1 = 0.f;
#pragma unroll
        for (int nt = 0; nt < 8; nt++) {
            S[nt][0] = __expf(S[nt][0] - nm0); s0 += S[nt][0];
            S[nt][1] = __expf(S[nt][1] - nm0); s0 += S[nt][1];
            S[nt][2] = __expf(S[nt][2] - nm1); s1 += S[nt][2];
            S[nt][3] = __expf(S[nt][3] - nm1); s1 += S[nt][3];
        }
        s0 += __shfl_xor_sync(0xffffffffu, s0, 1);
        s0 += __shfl_xor_sync(0xffffffffu, s0, 2);
        s1 += __shfl_xor_sync(0xffffffffu, s1, 1);
        s1 += __shfl_xor_sync(0xffffffffu, s1, 2);
        l0 = l0 * a0 + s0; l1 = l1 * a1 + s1;
        m0 = nm0; m1 = nm1;
#pragma unroll
        for (int ct = 0; ct < 4; ct++) {
            oacc[ct][0] *= a0; oacc[ct][1] *= a0;
            oacc[ct][2] *= a1; oacc[ct][3] *= a1;
        }

        uint32_t* Pw = Ps + w * 16 * PPAD;
        {
            int r = lane >> 2;
#pragma unroll
            for (int nt = 0; nt < 8; nt++) {
                int cl = nt * 8 + 2 * (lane & 3);
                Pw[r * PPAD + cl]           = f2tf32(S[nt][0]);
                Pw[r * PPAD + cl + 1]       = f2tf32(S[nt][1]);
                Pw[(r + 8) * PPAD + cl]     = f2tf32(S[nt][2]);
                Pw[(r + 8) * PPAD + cl + 1] = f2tf32(S[nt][3]);
            }
        }
        __syncwarp();

#pragma unroll
        for (int ks = 0; ks < 8; ks++) {
            uint32_t pf[4];
            int r = lane >> 2, c = ks * 8 + (lane & 3);
            pf[0] = Pw[r * PPAD + c];       pf[1] = Pw[(r + 8) * PPAD + c];
            pf[2] = Pw[r * PPAD + c + 4];   pf[3] = Pw[(r + 8) * PPAD + c + 4];
#pragma unroll
            for (int ct = 0; ct < 4; ct++) {
                uint32_t bf[2];
                int key = ks * 8 + (lane & 3);
                int ch  = ct * 8 + (lane >> 2);
                bf[0] = Vs[key * KPAD + ch];
                bf[1] = Vs[(key + 4) * KPAD + ch];
                mma8(oacc[ct], pf, bf);
            }
        }
    }

    float il0 = 1.f / l0, il1 = 1.f / l1;
    size_t row = (size_t)((b << 10) + qrow0 + (lane >> 2));
#pragma unroll
    for (int ct = 0; ct < 4; ct++) {
        int col = h * HC + ct * 8 + 2 * (lane & 3);
        float2 o0 = make_float2(oacc[ct][0] * il0, oacc[ct][1] * il0);
        float2 o1 = make_float2(oacc[ct][2] * il1, oacc[ct][3] * il1);
        *(float2*)&g_ao[row * NC + col]       = o0;
        *(float2*)&g_ao[(row + 8) * NC + col] = o1;
    }
}

// ======================================================================
// Host launcher
// ======================================================================
extern "C" void kernel_launch(void* const* d_in, const int* in_sizes, int n_in,
                              void* d_out, int out_size)
{
    (void)in_sizes; (void)n_in; (void)out_size;
    const float* x      = (const float*)d_in[0];
    const float* w_q    = (const float*)d_in[1];
    const float* b_q    = (const float*)d_in[2];
    const float* w_off0 = (const float*)d_in[3];
    const float* b_off0 = (const float*)d_in[4];
    const float* ln_g   = (const float*)d_in[5];
    const float* ln_b   = (const float*)d_in[6];
    const float* w_offp = (const float*)d_in[7];
    const float* w_k    = (const float*)d_in[8];
    const float* b_k    = (const float*)d_in[9];
    const float* w_v    = (const float*)d_in[10];
    const float* b_v    = (const float*)d_in[11];
    const float* w_o    = (const float*)d_in[12];
    const float* b_o    = (const float*)d_in[13];
    float* out = (float*)d_out;

    float *pq, *pxs, *pao;
    cudaGetSymbolAddress((void**)&pq,  g_q);
    cudaGetSymbolAddress((void**)&pxs, g_xs);
    cudaGetSymbolAddress((void**)&pao, g_ao);

    const dim3 gemm_grid(NC / 64, MTOT / 128);   // (6, 64)

    // 1) q = x @ w_q + b_q   (3xTF32, protects offset branch)
    gemm3_tf32<<<gemm_grid, 256>>>(x, w_q, b_q, pq, MTOT, NC, NC);
    // 2) grouped conv -> g_t (1xTF32; coord errors average out)
    conv1_tf32<<<dim3(MTOT / 128, NGROUP), 256>>>(w_off0, b_off0);
    // 3) LN + GELU + offset proj + warp coords (fp32)
    ln_offset_kernel<<<MTOT, 128>>>(ln_g, ln_b, w_offp);
    // 4) bilinear sampling (fp32)
    sample_kernel<<<dim3(256, BATCH * NGROUP), 256>>>(x);
    // 5) fused k,v projections (1xTF32 — attention rounds them anyway)
    kv_gemm1_tf32<<<gemm_grid, 256>>>(pxs, w_k, b_k, w_v, b_v);
    // 6) flash attention (1xTF32)
    const int attn_smem = (64 * KPAD * 2 + 8 * 16 * PPAD) * (int)sizeof(uint32_t);
    cudaFuncSetAttribute(attn_tf32, cudaFuncAttributeMaxDynamicSharedMemorySize, attn_smem);
    attn_tf32<<<dim3(8, NHEAD, BATCH), 256, attn_smem>>>();
    // 7) y = attn_out @ w_o + b_o (3xTF32, final un-averaged GEMM)
    gemm3_tf32<<<gemm_grid, 256>>>(pao, w_o, b_o, out, MTOT, NC, NC);
}